// round 12
// baseline (speedup 1.0000x reference)
#include <cuda_runtime.h>

// B3-spline UWT (a trous), J=3. x:(16,1024,1024)f32 -> (16,4,1024,1024)f32.
// Kernel A fuses levels 1+2: h1 = H1(x) in smem, then per-warp register
// streams compute c1 (5-tap) and u = V2*V1(h1) (composed 13-tap) together;
// c2 = H2(u) via shuffles. Kernel B = level-3 register/shuffle engine with
// prev rows captured from the load stream (no reload).

#define HH 1024
#define WW 1024
#define BB 16
#define HW (HH * WW)

__device__ float g_c2[BB * HW];

__device__ __forceinline__ int refl(int i, int L) {
    if (i < 0) i = -i;
    if (i >= L) i = 2 * L - 2 - i;
    return i;
}

__device__ __forceinline__ float4 shfl_up4(float4 v, int d) {
    float4 r;
    r.x = __shfl_up_sync(0xFFFFFFFFu, v.x, d);
    r.y = __shfl_up_sync(0xFFFFFFFFu, v.y, d);
    r.z = __shfl_up_sync(0xFFFFFFFFu, v.z, d);
    r.w = __shfl_up_sync(0xFFFFFFFFu, v.w, d);
    return r;
}
__device__ __forceinline__ float4 shfl_dn4(float4 v, int d) {
    float4 r;
    r.x = __shfl_down_sync(0xFFFFFFFFu, v.x, d);
    r.y = __shfl_down_sync(0xFFFFFFFFu, v.y, d);
    r.z = __shfl_down_sync(0xFFFFFFFFu, v.z, d);
    r.w = __shfl_down_sync(0xFFFFFFFFu, v.w, d);
    return r;
}

__device__ __forceinline__ float4 ldslow4(const float* row, int g0) {
    float4 v;
    v.x = row[refl(g0 + 0, WW)];
    v.y = row[refl(g0 + 1, WW)];
    v.z = row[refl(g0 + 2, WW)];
    v.w = row[refl(g0 + 3, WW)];
    return v;
}

__device__ __forceinline__ float4 f4axpy(float4 a, float w, float4 v) {
    a.x += w * v.x; a.y += w * v.y; a.z += w * v.z; a.w += w * v.w;
    return a;
}

// ======================= Kernel A: levels 1+2 fused =======================
// Tile: 32 out rows x 120 out cols. h1 rows [-6,38) (44), cols [-4,124).
__global__ __launch_bounds__(256, 5) void uwt_l12(
    const float* __restrict__ in,     // (B,H,W)
    float* __restrict__ out,          // w1 plane +0, w2 plane +HW (bstride 4*HW)
    float* __restrict__ c2p)          // bstride HW
{
    constexpr int TXO = 120;

    __shared__ float s_h1[44][128];

    const int b    = blockIdx.z;
    const int ty0  = blockIdx.y * 32;
    const int tx0  = blockIdx.x * TXO;
    const int tid  = threadIdx.x;
    const int w    = tid >> 5;
    const int lane = tid & 31;

    const float* base = in + b * HW;
    const int  gx    = tx0 - 4 + 4 * lane;
    const bool colIn = (gx >= 0) && (gx + 3 < WW);

    const float w0 = 0.0625f, w1 = 0.25f, w2 = 0.375f;
    const float W5[5] = { w0, w1, w2, w1, w0 };
    // V2*V1 composed 13-tap: [1,4,10,20,31,40,44,40,31,20,10,4,1]/256
    const float U13[13] = {
        0.00390625f, 0.015625f, 0.0390625f, 0.078125f, 0.12109375f,
        0.15625f, 0.171875f, 0.15625f, 0.12109375f, 0.078125f,
        0.0390625f, 0.015625f, 0.00390625f };

    // ---- Phase 1a: horizontal conv (DIL=1) of x rows -> s_h1 ----
    for (int hr = w; hr < 44; hr += 8) {
        const int gy = refl(ty0 - 6 + hr, HH);
        const float* row = base + gy * WW;
        float4 v = colIn ? *(const float4*)(row + gx) : ldslow4(row, gx);

        float t[12];
        *(float4*)&t[4] = v;
        float4 a = shfl_up4(v, 1);
        if (lane == 0)  a = ldslow4(row, gx - 4);
        *(float4*)&t[0] = a;
        float4 p = shfl_dn4(v, 1);
        if (lane == 31) p = ldslow4(row, gx + 4);
        *(float4*)&t[8] = p;

        float4 h;
        h.x = w0 * (t[2] + t[6]) + w1 * (t[3] + t[5]) + w2 * t[4];
        h.y = w0 * (t[3] + t[7]) + w1 * (t[4] + t[6]) + w2 * t[5];
        h.z = w0 * (t[4] + t[8]) + w1 * (t[5] + t[7]) + w2 * t[6];
        h.w = w0 * (t[5] + t[9]) + w1 * (t[6] + t[8]) + w2 * t[7];
        *(float4*)&s_h1[hr][4 * lane] = h;
    }
    __syncthreads();

    const bool doout = (lane >= 1) && (lane <= 30) && (gx < WW);
    float* w1p = out + b * 4 * HW;          // w1 plane
    float* w2p = out + b * 4 * HW + HW;     // w2 plane
    float* c2o = c2p + b * HW;

    // ---- Phase 2: per-warp 4-row chain; stream 16 h1 rows -> c1, u ----
    // Output rows R = ty0 + r0 + i. c1 taps s_h1[r0+i+4 .. +8] (W5);
    // u taps s_h1[r0+i .. r0+i+12] (U13). Max index r0+15 = 43.
    const int r0 = 4 * w;

    float4 c1[4], u[4];
    #pragma unroll
    for (int i = 0; i < 4; i++) {
        c1[i] = make_float4(0.f, 0.f, 0.f, 0.f);
        u[i]  = make_float4(0.f, 0.f, 0.f, 0.f);
    }

    #pragma unroll
    for (int j = 0; j < 16; j++) {
        float4 v = *(const float4*)&s_h1[r0 + j][4 * lane];
        #pragma unroll
        for (int i = 0; i < 4; i++) {
            const int k = j - i;            // U13 tap index
            if (k >= 0 && k <= 12) u[i] = f4axpy(u[i], U13[k], v);
            const int k2 = j - i - 4;       // W5 tap index
            if (k2 >= 0 && k2 <= 4) c1[i] = f4axpy(c1[i], W5[k2], v);
        }
    }

    #pragma unroll
    for (int i = 0; i < 4; i++) {
        float t[12];
        *(float4*)&t[4] = u[i];
        *(float4*)&t[0] = shfl_up4(u[i], 1);
        *(float4*)&t[8] = shfl_dn4(u[i], 1);

        if (doout) {
            float4 c2;                      // H2: taps +-2, +-4 floats
            c2.x = w0 * (t[0] + t[8])  + w1 * (t[2] + t[6])  + w2 * t[4];
            c2.y = w0 * (t[1] + t[9])  + w1 * (t[3] + t[7])  + w2 * t[5];
            c2.z = w0 * (t[2] + t[10]) + w1 * (t[4] + t[8])  + w2 * t[6];
            c2.w = w0 * (t[3] + t[11]) + w1 * (t[5] + t[9])  + w2 * t[7];

            const int off = (ty0 + r0 + i) * WW + gx;
            float4 prev = __ldg((const float4*)(base + off));   // L1 hit
            float4 d1 = make_float4(prev.x - c1[i].x, prev.y - c1[i].y,
                                    prev.z - c1[i].z, prev.w - c1[i].w);
            float4 d2 = make_float4(c1[i].x - c2.x, c1[i].y - c2.y,
                                    c1[i].z - c2.z, c1[i].w - c2.w);
            *(float4*)(w1p + off) = d1;
            *(float4*)(w2p + off) = d2;
            *(float4*)(c2o + off) = c2;
        }
    }
}

// ======================= Kernel B: level 3 =======================
template <int DIL>
__global__ __launch_bounds__(256, 5) void uwt_level(
    const float* __restrict__ in,
    float* __restrict__ detail,
    float* __restrict__ smooth,
    int sm_bs)
{
    constexpr int NB = (DIL == 4) ? 2 : 1;
    constexpr int CB = 4 * NB;

    const int b    = blockIdx.z;
    const int ty0  = blockIdx.y * 32;
    const int tid  = threadIdx.x;
    const int w    = tid >> 5;
    const int lane = tid & 31;

    constexpr int TXO = 4 * (32 - 2 * NB);
    const int gxv = blockIdx.x * TXO + 4 * (lane - NB);

    const float* base = in + b * HW;
    const float w0 = 0.0625f, w1 = 0.25f, w2 = 0.375f;
    const float W5[5] = { w0, w1, w2, w1, w0 };

    const int r0 = (w / DIL) * (4 * DIL) + (w % DIL);
    const bool colIn = (gxv >= 0) && (gxv + 3 < WW);

    float4 acc[4], pv[4];
    #pragma unroll
    for (int i = 0; i < 4; i++) acc[i] = make_float4(0.f, 0.f, 0.f, 0.f);

    #pragma unroll
    for (int j = 0; j < 8; j++) {
        const int gy = refl(ty0 + r0 + (j - 2) * DIL, HH);
        const float* row = base + gy * WW;
        float4 vj = colIn ? *(const float4*)(row + gxv) : ldslow4(row, gxv);
        if (j >= 2 && j <= 5) pv[j - 2] = vj;     // prev for output row i=j-2
        #pragma unroll
        for (int i = 0; i < 4; i++) {
            const int k = j - i;
            if (k >= 0 && k <= 4) acc[i] = f4axpy(acc[i], W5[k], vj);
        }
    }

    const bool doout = (lane >= NB) && (lane < 32 - NB) && (gxv < WW);

    #pragma unroll
    for (int i = 0; i < 4; i++) {
        float t[4 * (2 * NB + 1)];
        *(float4*)&t[CB] = acc[i];
        #pragma unroll
        for (int d = 1; d <= NB; d++) {
            *(float4*)&t[4 * (NB - d)] = shfl_up4(acc[i], d);
            *(float4*)&t[4 * (NB + d)] = shfl_dn4(acc[i], d);
        }

        if (doout) {
            float4 sm;
            sm.x = w0 * (t[CB + 0 - 2*DIL] + t[CB + 0 + 2*DIL])
                 + w1 * (t[CB + 0 -   DIL] + t[CB + 0 +   DIL]) + w2 * t[CB + 0];
            sm.y = w0 * (t[CB + 1 - 2*DIL] + t[CB + 1 + 2*DIL])
                 + w1 * (t[CB + 1 -   DIL] + t[CB + 1 +   DIL]) + w2 * t[CB + 1];
            sm.z = w0 * (t[CB + 2 - 2*DIL] + t[CB + 2 + 2*DIL])
                 + w1 * (t[CB + 2 -   DIL] + t[CB + 2 +   DIL]) + w2 * t[CB + 2];
            sm.w = w0 * (t[CB + 3 - 2*DIL] + t[CB + 3 + 2*DIL])
                 + w1 * (t[CB + 3 -   DIL] + t[CB + 3 +   DIL]) + w2 * t[CB + 3];

            const int off = (ty0 + r0 + i * DIL) * WW + gxv;
            float4 dt = make_float4(pv[i].x - sm.x, pv[i].y - sm.y,
                                    pv[i].z - sm.z, pv[i].w - sm.w);

            *(float4*)(detail + b * 4 * HW + off) = dt;
            *(float4*)(smooth + b * sm_bs  + off) = sm;
        }
    }
}

extern "C" void kernel_launch(void* const* d_in, const int* in_sizes, int n_in,
                              void* d_out, int out_size)
{
    (void)in_sizes; (void)n_in; (void)out_size;
    const float* x = (const float*)d_in[0];
    float* out = (float*)d_out;

    float* c2;
    cudaGetSymbolAddress((void**)&c2, g_c2);

    dim3 block(256);
    dim3 gridA((WW + 119) / 120, HH / 32, BB);   // 9 x-tiles
    dim3 gridB((WW + 111) / 112, HH / 32, BB);   // 10 x-tiles (DIL=4)

    uwt_l12<<<gridA, block>>>(x, out, c2);
    uwt_level<4><<<gridB, block>>>(c2, out + 2 * HW, out + 3 * HW, 4 * HW);
}

// round 13
// speedup vs baseline: 1.0514x; 1.0514x over previous
#include <cuda_runtime.h>

// B3-spline UWT (a trous), J=3, FULLY FUSED: one kernel computes w1,w2,w3,c3
// per 32x96 tile. x:(16,1024,1024)f32 -> (16,4,1024,1024)f32.
// No global intermediates: h1/c1/h2/c2 live in shared memory.
// DRAM traffic: 64MB read + 256MB write (vs 448MB in the 2-kernel version).

#define HH 1024
#define WW 1024
#define BB 16
#define HW (HH * WW)

#define SMW 120                      // smem row width (floats), 30 vec4 cols
#define ROWS_A 60                    // h1 / h2 buffer rows
#define ROWS_B 56                    // c1 / c2 buffer rows
#define SMEM_BYTES ((ROWS_A + ROWS_B) * SMW * 4)

__device__ __forceinline__ int refl(int i, int L) {
    if (i < 0) i = -i;
    if (i >= L) i = 2 * L - 2 - i;
    return i;
}

__device__ __forceinline__ float4 shfl_up4(float4 v, int d) {
    float4 r;
    r.x = __shfl_up_sync(0xFFFFFFFFu, v.x, d);
    r.y = __shfl_up_sync(0xFFFFFFFFu, v.y, d);
    r.z = __shfl_up_sync(0xFFFFFFFFu, v.z, d);
    r.w = __shfl_up_sync(0xFFFFFFFFu, v.w, d);
    return r;
}
__device__ __forceinline__ float4 shfl_dn4(float4 v, int d) {
    float4 r;
    r.x = __shfl_down_sync(0xFFFFFFFFu, v.x, d);
    r.y = __shfl_down_sync(0xFFFFFFFFu, v.y, d);
    r.z = __shfl_down_sync(0xFFFFFFFFu, v.z, d);
    r.w = __shfl_down_sync(0xFFFFFFFFu, v.w, d);
    return r;
}

__device__ __forceinline__ float4 ldslow4(const float* row, int g0) {
    float4 v;
    v.x = row[refl(g0 + 0, WW)];
    v.y = row[refl(g0 + 1, WW)];
    v.z = row[refl(g0 + 2, WW)];
    v.w = row[refl(g0 + 3, WW)];
    return v;
}

#define KW0 0.0625f
#define KW1 0.25f
#define KW2 0.375f

// vertical 5-tap on a float4 window
__device__ __forceinline__ float4 v5(const float4* win) {
    float4 r;
    r.x = KW0 * (win[0].x + win[4].x) + KW1 * (win[1].x + win[3].x) + KW2 * win[2].x;
    r.y = KW0 * (win[0].y + win[4].y) + KW1 * (win[1].y + win[3].y) + KW2 * win[2].y;
    r.z = KW0 * (win[0].z + win[4].z) + KW1 * (win[1].z + win[3].z) + KW2 * win[2].z;
    r.w = KW0 * (win[0].w + win[4].w) + KW1 * (win[1].w + win[3].w) + KW2 * win[2].w;
    return r;
}

__device__ __forceinline__ float4 f4axpy(float4 a, float w, float4 v) {
    a.x += w * v.x; a.y += w * v.y; a.z += w * v.z; a.w += w * v.w;
    return a;
}

__global__ __launch_bounds__(256, 4) void uwt_fused(
    const float* __restrict__ in,    // (B,H,W)
    float* __restrict__ out)         // (B,4,H,W)
{
    extern __shared__ float smbuf[];
    float (*s_a)[SMW] = (float(*)[SMW])smbuf;                    // h1 -> h2
    float (*s_b)[SMW] = (float(*)[SMW])(smbuf + ROWS_A * SMW);   // c1 -> c2

    const int b    = blockIdx.z;
    const int ty0  = blockIdx.y * 32;
    const int tx0  = blockIdx.x * 96;
    const int tid  = threadIdx.x;
    const int w    = tid >> 5;
    const int lane = tid & 31;

    const float* base = in + b * HW;
    float* w1p = out + b * 4 * HW;
    float* w2p = w1p + HW;
    float* w3p = w1p + 2 * HW;
    float* c3p = w1p + 3 * HW;

    // smem vec-col k <-> image col tx0 - 12 + 4k, k in [0,30)
    const int k   = lane;
    const int gxo = tx0 + 4 * k - 12;                // output col for lane k
    const bool kOut = (k >= 3) && (k < 27) && (gxo < WW);

    // ---- P1: h1 = H1(x), rows hr in [0,60), image row ty0-14+hr -----------
    {
        const int gx = tx0 - 16 + 4 * lane;          // P1 load col
        const bool colIn = (gx >= 0) && (gx + 3 < WW);
        for (int hr = w; hr < ROWS_A; hr += 8) {
            const int gy = refl(ty0 - 14 + hr, HH);
            const float* row = base + gy * WW;
            float4 v = colIn ? *(const float4*)(row + gx) : ldslow4(row, gx);

            float t[12];
            *(float4*)&t[4] = v;
            *(float4*)&t[0] = shfl_up4(v, 1);        // halo lanes supply edges
            *(float4*)&t[8] = shfl_dn4(v, 1);

            if (lane >= 1 && lane <= 30) {
                float4 h;
                h.x = KW0 * (t[2] + t[6]) + KW1 * (t[3] + t[5]) + KW2 * t[4];
                h.y = KW0 * (t[3] + t[7]) + KW1 * (t[4] + t[6]) + KW2 * t[5];
                h.z = KW0 * (t[4] + t[8]) + KW1 * (t[5] + t[7]) + KW2 * t[6];
                h.w = KW0 * (t[5] + t[9]) + KW1 * (t[6] + t[8]) + KW2 * t[7];
                *(float4*)&s_a[hr][4 * (lane - 1)] = h;
            }
        }
    }
    __syncthreads();

    // ---- P2: c1 = V1(h1) chains (7 rows/warp) -> s_b; emit w1 -------------
    if (k < 30) {
        const int cr0 = 7 * w;                       // rows cr0..cr0+6
        float4 win[5];
        #pragma unroll
        for (int t = 0; t < 5; t++)
            win[t] = *(const float4*)&s_a[cr0 + t][4 * k];

        #pragma unroll
        for (int t5 = 0; t5 < 7; t5++) {
            const int cr = cr0 + t5;                 // image row ty0-12+cr
            float4 c1 = v5(win);
            *(float4*)&s_b[cr][4 * k] = c1;

            if (cr >= 12 && cr < 44 && kOut) {
                const int off = (ty0 + cr - 12) * WW + gxo;
                float4 prev = __ldg((const float4*)(base + off));
                float4 d = make_float4(prev.x - c1.x, prev.y - c1.y,
                                       prev.z - c1.z, prev.w - c1.w);
                *(float4*)(w1p + off) = d;
            }
            if (t5 < 6) {
                win[0] = win[1]; win[1] = win[2]; win[2] = win[3]; win[3] = win[4];
                win[4] = *(const float4*)&s_a[cr0 + t5 + 5][4 * k];
            }
        }
    }
    __syncthreads();

    // ---- P3: h2 = H2(c1) (taps +-2,+-4 cols), rows [0,56) -> s_a ----------
    for (int r = w; r < ROWS_B; r += 8) {
        if (k >= 1 && k < 29) {
            float t[12];
            *(float4*)&t[0] = *(const float4*)&s_b[r][4 * (k - 1)];
            *(float4*)&t[4] = *(const float4*)&s_b[r][4 * k];
            *(float4*)&t[8] = *(const float4*)&s_b[r][4 * (k + 1)];
            float4 h;
            h.x = KW0 * (t[0] + t[8])  + KW1 * (t[2] + t[6])  + KW2 * t[4];
            h.y = KW0 * (t[1] + t[9])  + KW1 * (t[3] + t[7])  + KW2 * t[5];
            h.z = KW0 * (t[2] + t[10]) + KW1 * (t[4] + t[8])  + KW2 * t[6];
            h.w = KW0 * (t[3] + t[11]) + KW1 * (t[5] + t[9])  + KW2 * t[7];
            *(float4*)&s_a[r][4 * k] = h;
        }
    }
    __syncthreads();

    // ---- P4: c2 = V2(h2) (6 rows/warp, two parity sub-chains); emit w2;
    //          c2 overwrites c1 in s_b at row zr+4 ---------------------------
    if (k < 30) {
        const int zr0 = 6 * w;                       // c2 rows zr0..zr0+5
        #pragma unroll
        for (int par = 0; par < 2; par++) {
            float4 win[5];
            #pragma unroll
            for (int t = 0; t < 5; t++)
                win[t] = *(const float4*)&s_a[zr0 + par + 2 * t][4 * k];

            #pragma unroll
            for (int t5 = 0; t5 < 3; t5++) {
                const int zr = zr0 + par + 2 * t5;   // image row ty0-8+zr
                float4 c2 = v5(win);
                float4 c1v = *(const float4*)&s_b[zr + 4][4 * k];  // read first
                *(float4*)&s_b[zr + 4][4 * k] = c2;                // then replace

                if (zr >= 8 && zr < 40 && kOut) {
                    const int off = (ty0 + zr - 8) * WW + gxo;
                    float4 d = make_float4(c1v.x - c2.x, c1v.y - c2.y,
                                           c1v.z - c2.z, c1v.w - c2.w);
                    *(float4*)(w2p + off) = d;
                }
                if (t5 < 2) {
                    win[0] = win[1]; win[1] = win[2]; win[2] = win[3]; win[3] = win[4];
                    win[4] = *(const float4*)&s_a[zr0 + par + 2 * t5 + 10][4 * k];
                }
            }
        }
    }
    __syncthreads();

    // ---- P5: level 3: u = V4(c2) register chains; c3 = H4(u) via shuffles;
    //          emit w3 = c2 - c3 and c3 -------------------------------------
    {
        const int r0 = (w >> 2) * 16 + (w & 3);      // out rows r0 + 4i
        const float W5[5] = { KW0, KW1, KW2, KW1, KW0 };

        float4 acc[4], pv[4];
        #pragma unroll
        for (int i = 0; i < 4; i++) acc[i] = make_float4(0.f, 0.f, 0.f, 0.f);

        #pragma unroll
        for (int j = 0; j < 8; j++) {
            const int sr = r0 + 12 + 4 * (j - 2);    // s_b row (c2 grid)
            float4 v = (k < 30) ? *(const float4*)&s_b[sr][4 * k]
                                : make_float4(0.f, 0.f, 0.f, 0.f);
            if (j >= 2 && j < 6) pv[j - 2] = v;      // c2 at out row i=j-2
            #pragma unroll
            for (int i = 0; i < 4; i++) {
                const int kk = j - i;
                if (kk >= 0 && kk <= 4) acc[i] = f4axpy(acc[i], W5[kk], v);
            }
        }

        #pragma unroll
        for (int i = 0; i < 4; i++) {
            float t[20];
            *(float4*)&t[8]  = acc[i];
            *(float4*)&t[4]  = shfl_up4(acc[i], 1);
            *(float4*)&t[0]  = shfl_up4(acc[i], 2);
            *(float4*)&t[12] = shfl_dn4(acc[i], 1);
            *(float4*)&t[16] = shfl_dn4(acc[i], 2);

            if (kOut) {
                float4 c3;                           // taps +-4, +-8 floats
                c3.x = KW0 * (t[0] + t[16]) + KW1 * (t[4] + t[12]) + KW2 * t[8];
                c3.y = KW0 * (t[1] + t[17]) + KW1 * (t[5] + t[13]) + KW2 * t[9];
                c3.z = KW0 * (t[2] + t[18]) + KW1 * (t[6] + t[14]) + KW2 * t[10];
                c3.w = KW0 * (t[3] + t[19]) + KW1 * (t[7] + t[15]) + KW2 * t[11];

                const int off = (ty0 + r0 + 4 * i) * WW + gxo;
                float4 d = make_float4(pv[i].x - c3.x, pv[i].y - c3.y,
                                       pv[i].z - c3.z, pv[i].w - c3.w);
                *(float4*)(w3p + off) = d;
                *(float4*)(c3p + off) = c3;
            }
        }
    }
}

extern "C" void kernel_launch(void* const* d_in, const int* in_sizes, int n_in,
                              void* d_out, int out_size)
{
    (void)in_sizes; (void)n_in; (void)out_size;
    const float* x = (const float*)d_in[0];
    float* out = (float*)d_out;

    cudaFuncSetAttribute(uwt_fused,
                         cudaFuncAttributeMaxDynamicSharedMemorySize, SMEM_BYTES);

    dim3 grid((WW + 95) / 96, HH / 32, BB);          // 11 x 32 x 16
    dim3 block(256);
    uwt_fused<<<grid, block, SMEM_BYTES>>>(x, out);
}

// round 14
// speedup vs baseline: 1.1919x; 1.1337x over previous
#include <cuda_runtime.h>

// B3-spline UWT (a trous), J=3. x:(16,1024,1024)f32 -> (16,4,1024,1024)f32.
// Kernel A fuses levels 1+2 (w1, w2, c2) with c1 staged in smem; kernel B is
// the register/shuffle level-3 engine. R14: interior-y fast paths with
// pointer-increment addressing (no refl / per-load IMAD on interior tiles).

#define HH 1024
#define WW 1024
#define BB 16
#define HW (HH * WW)

__device__ float g_c2[BB * HW];

__device__ __forceinline__ int refl(int i, int L) {
    if (i < 0) i = -i;
    if (i >= L) i = 2 * L - 2 - i;
    return i;
}

__device__ __forceinline__ float4 shfl_up4(float4 v, int d) {
    float4 r;
    r.x = __shfl_up_sync(0xFFFFFFFFu, v.x, d);
    r.y = __shfl_up_sync(0xFFFFFFFFu, v.y, d);
    r.z = __shfl_up_sync(0xFFFFFFFFu, v.z, d);
    r.w = __shfl_up_sync(0xFFFFFFFFu, v.w, d);
    return r;
}
__device__ __forceinline__ float4 shfl_dn4(float4 v, int d) {
    float4 r;
    r.x = __shfl_down_sync(0xFFFFFFFFu, v.x, d);
    r.y = __shfl_down_sync(0xFFFFFFFFu, v.y, d);
    r.z = __shfl_down_sync(0xFFFFFFFFu, v.z, d);
    r.w = __shfl_down_sync(0xFFFFFFFFu, v.w, d);
    return r;
}

__device__ __forceinline__ float4 ldslow4(const float* row, int g0) {
    float4 v;
    v.x = row[refl(g0 + 0, WW)];
    v.y = row[refl(g0 + 1, WW)];
    v.z = row[refl(g0 + 2, WW)];
    v.w = row[refl(g0 + 3, WW)];
    return v;
}

__device__ __forceinline__ float4 f4axpy(float4 a, float w, float4 v) {
    a.x += w * v.x; a.y += w * v.y; a.z += w * v.z; a.w += w * v.w;
    return a;
}

// ======================= Kernel A: levels 1+2 fused =======================
// Tile: 32 out rows x 120 out cols. c1 region: rows [-4,36), cols [-4,124).
// h1 (x horiz-conv) rows [-6,38) -> 44 smem rows.
__global__ __launch_bounds__(256, 5) void uwt_l12(
    const float* __restrict__ in,     // (B,H,W)
    float* __restrict__ out,          // w1 plane +0, w2 plane +HW (bstride 4*HW)
    float* __restrict__ c2p)          // bstride HW
{
    constexpr int TXO = 120;

    __shared__ float s_h1[44][128];
    __shared__ float s_c1[40][128];

    const int b    = blockIdx.z;
    const int ty0  = blockIdx.y * 32;
    const int tx0  = blockIdx.x * TXO;
    const int tid  = threadIdx.x;
    const int w    = tid >> 5;
    const int lane = tid & 31;

    const float* base = in + b * HW;
    const int  gx    = tx0 - 4 + 4 * lane;            // lane's column (c1 grid)
    const bool colIn = (gx >= 0) && (gx + 3 < WW);

    const float w0 = 0.0625f, w1 = 0.25f, w2 = 0.375f;

    // ---- Phase 1a: horizontal conv (DIL=1) of x rows -> s_h1 ----
    auto h1row = [&](const float* row, int hr) {
        float4 v = colIn ? *(const float4*)(row + gx) : ldslow4(row, gx);

        float t[12];
        *(float4*)&t[4] = v;
        float4 a = shfl_up4(v, 1);
        if (lane == 0)  a = ldslow4(row, gx - 4);
        *(float4*)&t[0] = a;
        float4 p = shfl_dn4(v, 1);
        if (lane == 31) p = ldslow4(row, gx + 4);
        *(float4*)&t[8] = p;

        float4 h;
        h.x = w0 * (t[2] + t[6]) + w1 * (t[3] + t[5]) + w2 * t[4];
        h.y = w0 * (t[3] + t[7]) + w1 * (t[4] + t[6]) + w2 * t[5];
        h.z = w0 * (t[4] + t[8]) + w1 * (t[5] + t[7]) + w2 * t[6];
        h.w = w0 * (t[5] + t[9]) + w1 * (t[6] + t[8]) + w2 * t[7];
        *(float4*)&s_h1[hr][4 * lane] = h;
    };

    // rows accessed: ty0-6 .. ty0+37 — interior unless first/last y-tile
    if ((ty0 >= 6) && (ty0 + 38 <= HH)) {
        const float* prow = base + (ty0 - 6 + w) * WW;
        #pragma unroll
        for (int hr = w; hr < 44; hr += 8, prow += 8 * WW)
            h1row(prow, hr);
    } else {
        for (int hr = w; hr < 44; hr += 8)
            h1row(base + refl(ty0 - 6 + hr, HH) * WW, hr);
    }
    __syncthreads();

    const bool doout = (lane >= 1) && (lane <= 30) && (gx < WW);
    float* w1p = out + b * 4 * HW;          // w1 plane
    float* w2p = out + b * 4 * HW + HW;     // w2 plane
    float* c2o = c2p + b * HW;

    // ---- Phase 1b: vertical conv (DIL=1) -> s_c1; w1 = x - c1 on tile ----
    {
        const int cr0 = 5 * w;              // c1 rows cr0..cr0+4
        float4 win[5];
        #pragma unroll
        for (int k = 0; k < 5; k++)
            win[k] = *(const float4*)&s_h1[cr0 + k][4 * lane];

        #pragma unroll
        for (int t5 = 0; t5 < 5; t5++) {
            const int cr = cr0 + t5;
            float4 c1;
            c1.x = w0 * (win[0].x + win[4].x) + w1 * (win[1].x + win[3].x) + w2 * win[2].x;
            c1.y = w0 * (win[0].y + win[4].y) + w1 * (win[1].y + win[3].y) + w2 * win[2].y;
            c1.z = w0 * (win[0].z + win[4].z) + w1 * (win[1].z + win[3].z) + w2 * win[2].z;
            c1.w = w0 * (win[0].w + win[4].w) + w1 * (win[1].w + win[3].w) + w2 * win[2].w;
            *(float4*)&s_c1[cr][4 * lane] = c1;

            if (cr >= 4 && cr < 36 && doout) {
                const int off = (ty0 + cr - 4) * WW + gx;
                float4 prev = __ldg((const float4*)(base + off));   // L1 hit
                float4 d = make_float4(prev.x - c1.x, prev.y - c1.y,
                                       prev.z - c1.z, prev.w - c1.w);
                *(float4*)(w1p + off) = d;
            }
            if (t5 < 4) {
                win[0] = win[1]; win[1] = win[2]; win[2] = win[3]; win[3] = win[4];
                win[4] = *(const float4*)&s_h1[cr0 + t5 + 5][4 * lane];
            }
        }
    }
    __syncthreads();

    // ---- Phase 2: level 2 (DIL=2): vertical from s_c1, horiz via shuffles ----
    {
        const int r0 = (w >> 1) * 8 + (w & 1);      // rows r0 + 2i, i=0..3
        float4 vwin[5];
        #pragma unroll
        for (int k = 0; k < 5; k++)
            vwin[k] = *(const float4*)&s_c1[r0 + 2 * k][4 * lane];

        #pragma unroll
        for (int i = 0; i < 4; i++) {
            const int rr = r0 + 2 * i;

            float4 vv;
            vv.x = w0 * (vwin[0].x + vwin[4].x) + w1 * (vwin[1].x + vwin[3].x) + w2 * vwin[2].x;
            vv.y = w0 * (vwin[0].y + vwin[4].y) + w1 * (vwin[1].y + vwin[3].y) + w2 * vwin[2].y;
            vv.z = w0 * (vwin[0].z + vwin[4].z) + w1 * (vwin[1].z + vwin[3].z) + w2 * vwin[2].z;
            vv.w = w0 * (vwin[0].w + vwin[4].w) + w1 * (vwin[1].w + vwin[3].w) + w2 * vwin[2].w;

            float t[12];
            *(float4*)&t[4] = vv;
            *(float4*)&t[0] = shfl_up4(vv, 1);      // lanes 0/31 halo-only
            *(float4*)&t[8] = shfl_dn4(vv, 1);

            if (doout) {
                float4 c2;                          // taps +-2, +-4 floats
                c2.x = w0 * (t[0] + t[8])  + w1 * (t[2] + t[6])  + w2 * t[4];
                c2.y = w0 * (t[1] + t[9])  + w1 * (t[3] + t[7])  + w2 * t[5];
                c2.z = w0 * (t[2] + t[10]) + w1 * (t[4] + t[8])  + w2 * t[6];
                c2.w = w0 * (t[3] + t[11]) + w1 * (t[5] + t[9])  + w2 * t[7];

                const float4 c1c = vwin[2];         // c1 at (rr, this col)
                float4 d = make_float4(c1c.x - c2.x, c1c.y - c2.y,
                                       c1c.z - c2.z, c1c.w - c2.w);
                const int off = (ty0 + rr) * WW + gx;
                *(float4*)(w2p + off) = d;
                *(float4*)(c2o + off) = c2;
            }
            if (i < 3) {
                vwin[0] = vwin[1]; vwin[1] = vwin[2]; vwin[2] = vwin[3]; vwin[3] = vwin[4];
                vwin[4] = *(const float4*)&s_c1[r0 + 2 * i + 10][4 * lane];
            }
        }
    }
}

// ======================= Kernel B: level 3 =======================
template <int DIL>
__global__ __launch_bounds__(256, 6) void uwt_level(
    const float* __restrict__ in,
    float* __restrict__ detail,
    float* __restrict__ smooth,
    int sm_bs)
{
    constexpr int NB = (DIL == 4) ? 2 : 1;
    constexpr int CB = 4 * NB;

    const int b    = blockIdx.z;
    const int ty0  = blockIdx.y * 32;
    const int tid  = threadIdx.x;
    const int w    = tid >> 5;
    const int lane = tid & 31;

    constexpr int TXO = 4 * (32 - 2 * NB);
    const int gxv = blockIdx.x * TXO + 4 * (lane - NB);

    const float* base = in + b * HW;
    const float w0 = 0.0625f, w1 = 0.25f, w2 = 0.375f;
    const float W5[5] = { w0, w1, w2, w1, w0 };

    const int r0 = (w / DIL) * (4 * DIL) + (w % DIL);
    const bool colIn = (gxv >= 0) && (gxv + 3 < WW);

    float4 acc[4];
    #pragma unroll
    for (int i = 0; i < 4; i++) acc[i] = make_float4(0.f, 0.f, 0.f, 0.f);

    auto accum = [&](float4 vj, int j) {
        #pragma unroll
        for (int i = 0; i < 4; i++) {
            const int k = j - i;
            if (k >= 0 && k <= 4) acc[i] = f4axpy(acc[i], W5[k], vj);
        }
    };

    // rows accessed: ty0 + r0 + (j-2)*DIL, j = 0..7
    if ((ty0 + r0 - 2 * DIL >= 0) && (ty0 + r0 + 5 * DIL < HH) && colIn) {
        const float* p = base + (ty0 + r0 - 2 * DIL) * WW + gxv;
        #pragma unroll
        for (int j = 0; j < 8; j++, p += DIL * WW)
            accum(*(const float4*)p, j);
    } else {
        #pragma unroll
        for (int j = 0; j < 8; j++) {
            const int gy = refl(ty0 + r0 + (j - 2) * DIL, HH);
            const float* row = base + gy * WW;
            float4 vj = colIn ? *(const float4*)(row + gxv) : ldslow4(row, gxv);
            accum(vj, j);
        }
    }

    const bool doout = (lane >= NB) && (lane < 32 - NB) && (gxv < WW);

    #pragma unroll
    for (int i = 0; i < 4; i++) {
        float t[4 * (2 * NB + 1)];
        *(float4*)&t[CB] = acc[i];
        #pragma unroll
        for (int d = 1; d <= NB; d++) {
            *(float4*)&t[4 * (NB - d)] = shfl_up4(acc[i], d);
            *(float4*)&t[4 * (NB + d)] = shfl_dn4(acc[i], d);
        }

        if (doout) {
            float4 sm;
            sm.x = w0 * (t[CB + 0 - 2*DIL] + t[CB + 0 + 2*DIL])
                 + w1 * (t[CB + 0 -   DIL] + t[CB + 0 +   DIL]) + w2 * t[CB + 0];
            sm.y = w0 * (t[CB + 1 - 2*DIL] + t[CB + 1 + 2*DIL])
                 + w1 * (t[CB + 1 -   DIL] + t[CB + 1 +   DIL]) + w2 * t[CB + 1];
            sm.z = w0 * (t[CB + 2 - 2*DIL] + t[CB + 2 + 2*DIL])
                 + w1 * (t[CB + 2 -   DIL] + t[CB + 2 +   DIL]) + w2 * t[CB + 2];
            sm.w = w0 * (t[CB + 3 - 2*DIL] + t[CB + 3 + 2*DIL])
                 + w1 * (t[CB + 3 -   DIL] + t[CB + 3 +   DIL]) + w2 * t[CB + 3];

            const int off = (ty0 + r0) * WW + i * (DIL * WW) + gxv;
            float4 prev = __ldg((const float4*)(base + off));
            float4 dt = make_float4(prev.x - sm.x, prev.y - sm.y,
                                    prev.z - sm.z, prev.w - sm.w);

            *(float4*)(detail + b * 4 * HW + off) = dt;
            *(float4*)(smooth + b * sm_bs  + off) = sm;
        }
    }
}

extern "C" void kernel_launch(void* const* d_in, const int* in_sizes, int n_in,
                              void* d_out, int out_size)
{
    (void)in_sizes; (void)n_in; (void)out_size;
    const float* x = (const float*)d_in[0];
    float* out = (float*)d_out;

    float* c2;
    cudaGetSymbolAddress((void**)&c2, g_c2);

    dim3 block(256);
    dim3 gridA((WW + 119) / 120, HH / 32, BB);   // 9 x-tiles
    dim3 gridB((WW + 111) / 112, HH / 32, BB);   // 10 x-tiles (DIL=4)

    uwt_l12<<<gridA, block>>>(x, out, c2);
    uwt_level<4><<<gridB, block>>>(c2, out + 2 * HW, out + 3 * HW, 4 * HW);
}

// round 15
// speedup vs baseline: 1.3016x; 1.0920x over previous
#include <cuda_runtime.h>

// B3-spline UWT (a trous), J=3. x:(16,1024,1024)f32 -> (16,4,1024,1024)f32.
// Kernel A fuses levels 1+2: vertical-first register chains compute c1
// (V1 stream + H1 shuffles, no h1 smem buffer), c1 staged in smem, level 2
// (DIL=2) from smem. Kernel B = level-3 register/shuffle engine (R14).

#define HH 1024
#define WW 1024
#define BB 16
#define HW (HH * WW)

__device__ float g_c2[BB * HW];

__device__ __forceinline__ int refl(int i, int L) {
    if (i < 0) i = -i;
    if (i >= L) i = 2 * L - 2 - i;
    return i;
}

__device__ __forceinline__ float4 shfl_up4(float4 v, int d) {
    float4 r;
    r.x = __shfl_up_sync(0xFFFFFFFFu, v.x, d);
    r.y = __shfl_up_sync(0xFFFFFFFFu, v.y, d);
    r.z = __shfl_up_sync(0xFFFFFFFFu, v.z, d);
    r.w = __shfl_up_sync(0xFFFFFFFFu, v.w, d);
    return r;
}
__device__ __forceinline__ float4 shfl_dn4(float4 v, int d) {
    float4 r;
    r.x = __shfl_down_sync(0xFFFFFFFFu, v.x, d);
    r.y = __shfl_down_sync(0xFFFFFFFFu, v.y, d);
    r.z = __shfl_down_sync(0xFFFFFFFFu, v.z, d);
    r.w = __shfl_down_sync(0xFFFFFFFFu, v.w, d);
    return r;
}

__device__ __forceinline__ float4 ldslow4(const float* row, int g0) {
    float4 v;
    v.x = row[refl(g0 + 0, WW)];
    v.y = row[refl(g0 + 1, WW)];
    v.z = row[refl(g0 + 2, WW)];
    v.w = row[refl(g0 + 3, WW)];
    return v;
}

__device__ __forceinline__ float4 f4axpy(float4 a, float w, float4 v) {
    a.x += w * v.x; a.y += w * v.y; a.z += w * v.z; a.w += w * v.w;
    return a;
}

#define KW0 0.0625f
#define KW1 0.25f
#define KW2 0.375f

// ======================= Kernel A: levels 1+2 fused =======================
// Tile: 32 out rows x 112 out cols. Lane k <-> x col gx = tx0-8+4k.
// c1 rows [-4,36) in smem (30 valid vec-cols = cols [tx0-4, tx0+116)).
__global__ __launch_bounds__(256, 6) void uwt_l12(
    const float* __restrict__ in,     // (B,H,W)
    float* __restrict__ out,          // w1 +0, w2 +HW (bstride 4*HW)
    float* __restrict__ c2p)          // bstride HW
{
    constexpr int TXO = 112;

    __shared__ float s_c1[40][120];

    const int b    = blockIdx.z;
    const int ty0  = blockIdx.y * 32;
    const int tx0  = blockIdx.x * TXO;
    const int tid  = threadIdx.x;
    const int w    = tid >> 5;
    const int lane = tid & 31;

    const float* base = in + b * HW;
    const int  gx    = tx0 - 8 + 4 * lane;
    const bool colIn = (gx >= 0) && (gx + 3 < WW);

    const float W5[5] = { KW0, KW1, KW2, KW1, KW0 };

    float* w1p = out + b * 4 * HW;
    float* w2p = w1p + HW;
    float* c2o = c2p + b * HW;

    // ---- P1: vertical-first chain of 5 c1 rows (cr0..cr0+4) ---------------
    {
        const int cr0 = 5 * w;                // c1 rows, image row ty0-4+cr
        const int yb  = ty0 - 6 + 5 * w;      // first streamed x row

        float4 acc[5];
        #pragma unroll
        for (int t = 0; t < 5; t++) acc[t] = make_float4(0.f, 0.f, 0.f, 0.f);

        if ((yb >= 0) && (yb + 8 < HH) && colIn) {
            const float* p = base + yb * WW + gx;
            #pragma unroll
            for (int j = 0; j < 9; j++, p += WW) {
                float4 v = *(const float4*)p;
                #pragma unroll
                for (int t = 0; t < 5; t++) {
                    const int k = j - t;
                    if (k >= 0 && k <= 4) acc[t] = f4axpy(acc[t], W5[k], v);
                }
            }
        } else {
            #pragma unroll
            for (int j = 0; j < 9; j++) {
                const float* row = base + refl(yb + j, HH) * WW;
                float4 v = colIn ? *(const float4*)(row + gx) : ldslow4(row, gx);
                #pragma unroll
                for (int t = 0; t < 5; t++) {
                    const int k = j - t;
                    if (k >= 0 && k <= 4) acc[t] = f4axpy(acc[t], W5[k], v);
                }
            }
        }

        // H1 via +-1 lane shuffles; lanes 1..30 produce valid c1
        #pragma unroll
        for (int t5 = 0; t5 < 5; t5++) {
            const int cr = cr0 + t5;
            float t[12];
            *(float4*)&t[4] = acc[t5];
            *(float4*)&t[0] = shfl_up4(acc[t5], 1);
            *(float4*)&t[8] = shfl_dn4(acc[t5], 1);

            if (lane >= 1 && lane <= 30) {
                float4 c1;
                c1.x = KW0 * (t[2] + t[6]) + KW1 * (t[3] + t[5]) + KW2 * t[4];
                c1.y = KW0 * (t[3] + t[7]) + KW1 * (t[4] + t[6]) + KW2 * t[5];
                c1.z = KW0 * (t[4] + t[8]) + KW1 * (t[5] + t[7]) + KW2 * t[6];
                c1.w = KW0 * (t[5] + t[9]) + KW1 * (t[6] + t[8]) + KW2 * t[7];
                *(float4*)&s_c1[cr][4 * (lane - 1)] = c1;

                // w1 = x - c1 on output cols (lanes 2..29) and rows [4,36)
                if (cr >= 4 && cr < 36 && lane >= 2 && lane <= 29 && gx < WW) {
                    const int off = (ty0 + cr - 4) * WW + gx;
                    float4 prev = __ldg((const float4*)(base + off));   // L1 hit
                    float4 d = make_float4(prev.x - c1.x, prev.y - c1.y,
                                           prev.z - c1.z, prev.w - c1.w);
                    *(float4*)(w1p + off) = d;
                }
            }
        }
    }
    __syncthreads();

    // ---- P2: level 2 (DIL=2) from s_c1; lane m <-> col tx0-4+4m -----------
    {
        const int gxo = tx0 - 4 + 4 * lane;
        const bool doout = (lane >= 1) && (lane <= 28) && (gxo < WW);
        const int r0 = (w >> 1) * 8 + (w & 1);      // c2 rows r0 + 2i

        float4 vwin[5];
        if (lane < 30) {
            #pragma unroll
            for (int k = 0; k < 5; k++)
                vwin[k] = *(const float4*)&s_c1[r0 + 2 * k][4 * lane];
        } else {
            #pragma unroll
            for (int k = 0; k < 5; k++) vwin[k] = make_float4(0.f, 0.f, 0.f, 0.f);
        }

        #pragma unroll
        for (int i = 0; i < 4; i++) {
            const int rr = r0 + 2 * i;

            float4 vv;
            vv.x = KW0 * (vwin[0].x + vwin[4].x) + KW1 * (vwin[1].x + vwin[3].x) + KW2 * vwin[2].x;
            vv.y = KW0 * (vwin[0].y + vwin[4].y) + KW1 * (vwin[1].y + vwin[3].y) + KW2 * vwin[2].y;
            vv.z = KW0 * (vwin[0].z + vwin[4].z) + KW1 * (vwin[1].z + vwin[3].z) + KW2 * vwin[2].z;
            vv.w = KW0 * (vwin[0].w + vwin[4].w) + KW1 * (vwin[1].w + vwin[3].w) + KW2 * vwin[2].w;

            float t[12];
            *(float4*)&t[4] = vv;
            *(float4*)&t[0] = shfl_up4(vv, 1);
            *(float4*)&t[8] = shfl_dn4(vv, 1);

            if (doout) {
                float4 c2;                          // H2: taps +-2, +-4 floats
                c2.x = KW0 * (t[0] + t[8])  + KW1 * (t[2] + t[6])  + KW2 * t[4];
                c2.y = KW0 * (t[1] + t[9])  + KW1 * (t[3] + t[7])  + KW2 * t[5];
                c2.z = KW0 * (t[2] + t[10]) + KW1 * (t[4] + t[8])  + KW2 * t[6];
                c2.w = KW0 * (t[3] + t[11]) + KW1 * (t[5] + t[9])  + KW2 * t[7];

                const float4 c1c = vwin[2];         // c1 at (rr, this col)
                float4 d = make_float4(c1c.x - c2.x, c1c.y - c2.y,
                                       c1c.z - c2.z, c1c.w - c2.w);
                const int off = (ty0 + rr) * WW + gxo;
                *(float4*)(w2p + off) = d;
                *(float4*)(c2o + off) = c2;
            }
            if (i < 3) {
                vwin[0] = vwin[1]; vwin[1] = vwin[2]; vwin[2] = vwin[3]; vwin[3] = vwin[4];
                if (lane < 30)
                    vwin[4] = *(const float4*)&s_c1[r0 + 2 * i + 10][4 * lane];
            }
        }
    }
}

// ======================= Kernel B: level 3 (R14) =======================
template <int DIL>
__global__ __launch_bounds__(256, 6) void uwt_level(
    const float* __restrict__ in,
    float* __restrict__ detail,
    float* __restrict__ smooth,
    int sm_bs)
{
    constexpr int NB = (DIL == 4) ? 2 : 1;
    constexpr int CB = 4 * NB;

    const int b    = blockIdx.z;
    const int ty0  = blockIdx.y * 32;
    const int tid  = threadIdx.x;
    const int w    = tid >> 5;
    const int lane = tid & 31;

    constexpr int TXO = 4 * (32 - 2 * NB);
    const int gxv = blockIdx.x * TXO + 4 * (lane - NB);

    const float* base = in + b * HW;
    const float W5[5] = { KW0, KW1, KW2, KW1, KW0 };

    const int r0 = (w / DIL) * (4 * DIL) + (w % DIL);
    const bool colIn = (gxv >= 0) && (gxv + 3 < WW);

    float4 acc[4];
    #pragma unroll
    for (int i = 0; i < 4; i++) acc[i] = make_float4(0.f, 0.f, 0.f, 0.f);

    auto accum = [&](float4 vj, int j) {
        #pragma unroll
        for (int i = 0; i < 4; i++) {
            const int k = j - i;
            if (k >= 0 && k <= 4) acc[i] = f4axpy(acc[i], W5[k], vj);
        }
    };

    if ((ty0 + r0 - 2 * DIL >= 0) && (ty0 + r0 + 5 * DIL < HH) && colIn) {
        const float* p = base + (ty0 + r0 - 2 * DIL) * WW + gxv;
        #pragma unroll
        for (int j = 0; j < 8; j++, p += DIL * WW)
            accum(*(const float4*)p, j);
    } else {
        #pragma unroll
        for (int j = 0; j < 8; j++) {
            const int gy = refl(ty0 + r0 + (j - 2) * DIL, HH);
            const float* row = base + gy * WW;
            float4 vj = colIn ? *(const float4*)(row + gxv) : ldslow4(row, gxv);
            accum(vj, j);
        }
    }

    const bool doout = (lane >= NB) && (lane < 32 - NB) && (gxv < WW);

    #pragma unroll
    for (int i = 0; i < 4; i++) {
        float t[4 * (2 * NB + 1)];
        *(float4*)&t[CB] = acc[i];
        #pragma unroll
        for (int d = 1; d <= NB; d++) {
            *(float4*)&t[4 * (NB - d)] = shfl_up4(acc[i], d);
            *(float4*)&t[4 * (NB + d)] = shfl_dn4(acc[i], d);
        }

        if (doout) {
            float4 sm;
            sm.x = KW0 * (t[CB + 0 - 2*DIL] + t[CB + 0 + 2*DIL])
                 + KW1 * (t[CB + 0 -   DIL] + t[CB + 0 +   DIL]) + KW2 * t[CB + 0];
            sm.y = KW0 * (t[CB + 1 - 2*DIL] + t[CB + 1 + 2*DIL])
                 + KW1 * (t[CB + 1 -   DIL] + t[CB + 1 +   DIL]) + KW2 * t[CB + 1];
            sm.z = KW0 * (t[CB + 2 - 2*DIL] + t[CB + 2 + 2*DIL])
                 + KW1 * (t[CB + 2 -   DIL] + t[CB + 2 +   DIL]) + KW2 * t[CB + 2];
            sm.w = KW0 * (t[CB + 3 - 2*DIL] + t[CB + 3 + 2*DIL])
                 + KW1 * (t[CB + 3 -   DIL] + t[CB + 3 +   DIL]) + KW2 * t[CB + 3];

            const int off = (ty0 + r0) * WW + i * (DIL * WW) + gxv;
            float4 prev = __ldg((const float4*)(base + off));
            float4 dt = make_float4(prev.x - sm.x, prev.y - sm.y,
                                    prev.z - sm.z, prev.w - sm.w);

            *(float4*)(detail + b * 4 * HW + off) = dt;
            *(float4*)(smooth + b * sm_bs  + off) = sm;
        }
    }
}

extern "C" void kernel_launch(void* const* d_in, const int* in_sizes, int n_in,
                              void* d_out, int out_size)
{
    (void)in_sizes; (void)n_in; (void)out_size;
    const float* x = (const float*)d_in[0];
    float* out = (float*)d_out;

    float* c2;
    cudaGetSymbolAddress((void**)&c2, g_c2);

    dim3 block(256);
    dim3 gridA((WW + 111) / 112, HH / 32, BB);   // 10 x-tiles
    dim3 gridB((WW + 111) / 112, HH / 32, BB);   // 10 x-tiles (DIL=4)

    uwt_l12<<<gridA, block>>>(x, out, c2);
    uwt_level<4><<<gridB, block>>>(c2, out + 2 * HW, out + 3 * HW, 4 * HW);
}

// round 16
// speedup vs baseline: 1.3035x; 1.0014x over previous
#include <cuda_runtime.h>

// B3-spline UWT (a trous), J=3. x:(16,1024,1024)f32 -> (16,4,1024,1024)f32.
// Kernel A fuses levels 1+2 (vertical-first register chains + H via shuffles,
// c1 staged in smem); kernel B = level-3 register/shuffle engine.
// R16: streaming stores (__stcs) for final outputs so c2 stays L2-resident.

#define HH 1024
#define WW 1024
#define BB 16
#define HW (HH * WW)

__device__ float g_c2[BB * HW];

__device__ __forceinline__ int refl(int i, int L) {
    if (i < 0) i = -i;
    if (i >= L) i = 2 * L - 2 - i;
    return i;
}

__device__ __forceinline__ float4 shfl_up4(float4 v, int d) {
    float4 r;
    r.x = __shfl_up_sync(0xFFFFFFFFu, v.x, d);
    r.y = __shfl_up_sync(0xFFFFFFFFu, v.y, d);
    r.z = __shfl_up_sync(0xFFFFFFFFu, v.z, d);
    r.w = __shfl_up_sync(0xFFFFFFFFu, v.w, d);
    return r;
}
__device__ __forceinline__ float4 shfl_dn4(float4 v, int d) {
    float4 r;
    r.x = __shfl_down_sync(0xFFFFFFFFu, v.x, d);
    r.y = __shfl_down_sync(0xFFFFFFFFu, v.y, d);
    r.z = __shfl_down_sync(0xFFFFFFFFu, v.z, d);
    r.w = __shfl_down_sync(0xFFFFFFFFu, v.w, d);
    return r;
}

__device__ __forceinline__ float4 ldslow4(const float* row, int g0) {
    float4 v;
    v.x = row[refl(g0 + 0, WW)];
    v.y = row[refl(g0 + 1, WW)];
    v.z = row[refl(g0 + 2, WW)];
    v.w = row[refl(g0 + 3, WW)];
    return v;
}

__device__ __forceinline__ float4 f4axpy(float4 a, float w, float4 v) {
    a.x += w * v.x; a.y += w * v.y; a.z += w * v.z; a.w += w * v.w;
    return a;
}

#define KW0 0.0625f
#define KW1 0.25f
#define KW2 0.375f

// ======================= Kernel A: levels 1+2 fused =======================
__global__ __launch_bounds__(256, 6) void uwt_l12(
    const float* __restrict__ in,     // (B,H,W)
    float* __restrict__ out,          // w1 +0, w2 +HW (bstride 4*HW)
    float* __restrict__ c2p)          // bstride HW
{
    constexpr int TXO = 112;

    __shared__ float s_c1[40][120];

    const int b    = blockIdx.z;
    const int ty0  = blockIdx.y * 32;
    const int tx0  = blockIdx.x * TXO;
    const int tid  = threadIdx.x;
    const int w    = tid >> 5;
    const int lane = tid & 31;

    const float* base = in + b * HW;
    const int  gx    = tx0 - 8 + 4 * lane;
    const bool colIn = (gx >= 0) && (gx + 3 < WW);

    const float W5[5] = { KW0, KW1, KW2, KW1, KW0 };

    float* w1p = out + b * 4 * HW;
    float* w2p = w1p + HW;
    float* c2o = c2p + b * HW;

    // ---- P1: vertical-first chain of 5 c1 rows (cr0..cr0+4) ---------------
    {
        const int cr0 = 5 * w;                // c1 rows, image row ty0-4+cr
        const int yb  = ty0 - 6 + 5 * w;      // first streamed x row

        float4 acc[5];
        #pragma unroll
        for (int t = 0; t < 5; t++) acc[t] = make_float4(0.f, 0.f, 0.f, 0.f);

        if ((yb >= 0) && (yb + 8 < HH) && colIn) {
            const float* p = base + yb * WW + gx;
            #pragma unroll
            for (int j = 0; j < 9; j++, p += WW) {
                float4 v = *(const float4*)p;
                #pragma unroll
                for (int t = 0; t < 5; t++) {
                    const int k = j - t;
                    if (k >= 0 && k <= 4) acc[t] = f4axpy(acc[t], W5[k], v);
                }
            }
        } else {
            #pragma unroll
            for (int j = 0; j < 9; j++) {
                const float* row = base + refl(yb + j, HH) * WW;
                float4 v = colIn ? *(const float4*)(row + gx) : ldslow4(row, gx);
                #pragma unroll
                for (int t = 0; t < 5; t++) {
                    const int k = j - t;
                    if (k >= 0 && k <= 4) acc[t] = f4axpy(acc[t], W5[k], v);
                }
            }
        }

        // H1 via +-1 lane shuffles; lanes 1..30 produce valid c1
        #pragma unroll
        for (int t5 = 0; t5 < 5; t5++) {
            const int cr = cr0 + t5;
            float t[12];
            *(float4*)&t[4] = acc[t5];
            *(float4*)&t[0] = shfl_up4(acc[t5], 1);
            *(float4*)&t[8] = shfl_dn4(acc[t5], 1);

            if (lane >= 1 && lane <= 30) {
                float4 c1;
                c1.x = KW0 * (t[2] + t[6]) + KW1 * (t[3] + t[5]) + KW2 * t[4];
                c1.y = KW0 * (t[3] + t[7]) + KW1 * (t[4] + t[6]) + KW2 * t[5];
                c1.z = KW0 * (t[4] + t[8]) + KW1 * (t[5] + t[7]) + KW2 * t[6];
                c1.w = KW0 * (t[5] + t[9]) + KW1 * (t[6] + t[8]) + KW2 * t[7];
                *(float4*)&s_c1[cr][4 * (lane - 1)] = c1;

                if (cr >= 4 && cr < 36 && lane >= 2 && lane <= 29 && gx < WW) {
                    const int off = (ty0 + cr - 4) * WW + gx;
                    float4 prev = __ldg((const float4*)(base + off));   // L1 hit
                    float4 d = make_float4(prev.x - c1.x, prev.y - c1.y,
                                           prev.z - c1.z, prev.w - c1.w);
                    __stcs((float4*)(w1p + off), d);
                }
            }
        }
    }
    __syncthreads();

    // ---- P2: level 2 (DIL=2) from s_c1; lane m <-> col tx0-4+4m -----------
    {
        const int gxo = tx0 - 4 + 4 * lane;
        const bool doout = (lane >= 1) && (lane <= 28) && (gxo < WW);
        const int r0 = (w >> 1) * 8 + (w & 1);      // c2 rows r0 + 2i

        float4 vwin[5];
        if (lane < 30) {
            #pragma unroll
            for (int k = 0; k < 5; k++)
                vwin[k] = *(const float4*)&s_c1[r0 + 2 * k][4 * lane];
        } else {
            #pragma unroll
            for (int k = 0; k < 5; k++) vwin[k] = make_float4(0.f, 0.f, 0.f, 0.f);
        }

        #pragma unroll
        for (int i = 0; i < 4; i++) {
            const int rr = r0 + 2 * i;

            float4 vv;
            vv.x = KW0 * (vwin[0].x + vwin[4].x) + KW1 * (vwin[1].x + vwin[3].x) + KW2 * vwin[2].x;
            vv.y = KW0 * (vwin[0].y + vwin[4].y) + KW1 * (vwin[1].y + vwin[3].y) + KW2 * vwin[2].y;
            vv.z = KW0 * (vwin[0].z + vwin[4].z) + KW1 * (vwin[1].z + vwin[3].z) + KW2 * vwin[2].z;
            vv.w = KW0 * (vwin[0].w + vwin[4].w) + KW1 * (vwin[1].w + vwin[3].w) + KW2 * vwin[2].w;

            float t[12];
            *(float4*)&t[4] = vv;
            *(float4*)&t[0] = shfl_up4(vv, 1);
            *(float4*)&t[8] = shfl_dn4(vv, 1);

            if (doout) {
                float4 c2;                          // H2: taps +-2, +-4 floats
                c2.x = KW0 * (t[0] + t[8])  + KW1 * (t[2] + t[6])  + KW2 * t[4];
                c2.y = KW0 * (t[1] + t[9])  + KW1 * (t[3] + t[7])  + KW2 * t[5];
                c2.z = KW0 * (t[2] + t[10]) + KW1 * (t[4] + t[8])  + KW2 * t[6];
                c2.w = KW0 * (t[3] + t[11]) + KW1 * (t[5] + t[9])  + KW2 * t[7];

                const float4 c1c = vwin[2];         // c1 at (rr, this col)
                float4 d = make_float4(c1c.x - c2.x, c1c.y - c2.y,
                                       c1c.z - c2.z, c1c.w - c2.w);
                const int off = (ty0 + rr) * WW + gxo;
                __stcs((float4*)(w2p + off), d);
                __stcg((float4*)(c2o + off), c2);   // keep c2 in L2 for kernel B
            }
            if (i < 3) {
                vwin[0] = vwin[1]; vwin[1] = vwin[2]; vwin[2] = vwin[3]; vwin[3] = vwin[4];
                if (lane < 30)
                    vwin[4] = *(const float4*)&s_c1[r0 + 2 * i + 10][4 * lane];
            }
        }
    }
}

// ======================= Kernel B: level 3 =======================
template <int DIL>
__global__ __launch_bounds__(256, 6) void uwt_level(
    const float* __restrict__ in,
    float* __restrict__ detail,
    float* __restrict__ smooth,
    int sm_bs)
{
    constexpr int NB = (DIL == 4) ? 2 : 1;
    constexpr int CB = 4 * NB;

    const int b    = blockIdx.z;
    const int ty0  = blockIdx.y * 32;
    const int tid  = threadIdx.x;
    const int w    = tid >> 5;
    const int lane = tid & 31;

    constexpr int TXO = 4 * (32 - 2 * NB);
    const int gxv = blockIdx.x * TXO + 4 * (lane - NB);

    const float* base = in + b * HW;
    const float W5[5] = { KW0, KW1, KW2, KW1, KW0 };

    const int r0 = (w / DIL) * (4 * DIL) + (w % DIL);
    const bool colIn = (gxv >= 0) && (gxv + 3 < WW);

    float4 acc[4];
    #pragma unroll
    for (int i = 0; i < 4; i++) acc[i] = make_float4(0.f, 0.f, 0.f, 0.f);

    auto accum = [&](float4 vj, int j) {
        #pragma unroll
        for (int i = 0; i < 4; i++) {
            const int k = j - i;
            if (k >= 0 && k <= 4) acc[i] = f4axpy(acc[i], W5[k], vj);
        }
    };

    if ((ty0 + r0 - 2 * DIL >= 0) && (ty0 + r0 + 5 * DIL < HH) && colIn) {
        const float* p = base + (ty0 + r0 - 2 * DIL) * WW + gxv;
        #pragma unroll
        for (int j = 0; j < 8; j++, p += DIL * WW)
            accum(*(const float4*)p, j);
    } else {
        #pragma unroll
        for (int j = 0; j < 8; j++) {
            const int gy = refl(ty0 + r0 + (j - 2) * DIL, HH);
            const float* row = base + gy * WW;
            float4 vj = colIn ? *(const float4*)(row + gxv) : ldslow4(row, gxv);
            accum(vj, j);
        }
    }

    const bool doout = (lane >= NB) && (lane < 32 - NB) && (gxv < WW);

    #pragma unroll
    for (int i = 0; i < 4; i++) {
        float t[4 * (2 * NB + 1)];
        *(float4*)&t[CB] = acc[i];
        #pragma unroll
        for (int d = 1; d <= NB; d++) {
            *(float4*)&t[4 * (NB - d)] = shfl_up4(acc[i], d);
            *(float4*)&t[4 * (NB + d)] = shfl_dn4(acc[i], d);
        }

        if (doout) {
            float4 sm;
            sm.x = KW0 * (t[CB + 0 - 2*DIL] + t[CB + 0 + 2*DIL])
                 + KW1 * (t[CB + 0 -   DIL] + t[CB + 0 +   DIL]) + KW2 * t[CB + 0];
            sm.y = KW0 * (t[CB + 1 - 2*DIL] + t[CB + 1 + 2*DIL])
                 + KW1 * (t[CB + 1 -   DIL] + t[CB + 1 +   DIL]) + KW2 * t[CB + 1];
            sm.z = KW0 * (t[CB + 2 - 2*DIL] + t[CB + 2 + 2*DIL])
                 + KW1 * (t[CB + 2 -   DIL] + t[CB + 2 +   DIL]) + KW2 * t[CB + 2];
            sm.w = KW0 * (t[CB + 3 - 2*DIL] + t[CB + 3 + 2*DIL])
                 + KW1 * (t[CB + 3 -   DIL] + t[CB + 3 +   DIL]) + KW2 * t[CB + 3];

            const int off = (ty0 + r0) * WW + i * (DIL * WW) + gxv;
            float4 prev = __ldg((const float4*)(base + off));
            float4 dt = make_float4(prev.x - sm.x, prev.y - sm.y,
                                    prev.z - sm.z, prev.w - sm.w);

            __stcs((float4*)(detail + b * 4 * HW + off), dt);
            __stcs((float4*)(smooth + b * sm_bs  + off), sm);
        }
    }
}

extern "C" void kernel_launch(void* const* d_in, const int* in_sizes, int n_in,
                              void* d_out, int out_size)
{
    (void)in_sizes; (void)n_in; (void)out_size;
    const float* x = (const float*)d_in[0];
    float* out = (float*)d_out;

    float* c2;
    cudaGetSymbolAddress((void**)&c2, g_c2);

    dim3 block(256);
    dim3 gridA((WW + 111) / 112, HH / 32, BB);   // 10 x-tiles
    dim3 gridB((WW + 111) / 112, HH / 32, BB);   // 10 x-tiles (DIL=4)

    uwt_l12<<<gridA, block>>>(x, out, c2);
    uwt_level<4><<<gridB, block>>>(c2, out + 2 * HW, out + 3 * HW, 4 * HW);
}